// round 1
// baseline (speedup 1.0000x reference)
#include <cuda_runtime.h>
#include <cuda_bf16.h>
#include <cstdint>

// Problem constants
#define BGR   128          // graphs
#define N0    512          // nodes per graph, stage 1
#define EPG   4096         // edges per graph
#define ETOT  (BGR*EPG)    // 524288 edges
#define FDIM  128
#define NTMAX (BGR*N0)     // 65536

// ---------------- device scratch (no allocation allowed) ----------------
__device__ float g_bufA[NTMAX*FDIM];
__device__ float g_bufB[NTMAX*FDIM];
__device__ float g_dinv [NTMAX];
__device__ float g_s0   [NTMAX];
__device__ float g_score[NTMAX];
__device__ int   g_src[ETOT];
__device__ int   g_dst[ETOT];
__device__ int   g_csr_src[ETOT];
__device__ float g_csr_w [ETOT];
__device__ int   g_cnt   [NTMAX];
__device__ int   g_cursor[NTMAX];
__device__ int   g_off   [NTMAX];
__device__ int   g_topi  [BGR*256];
__device__ float g_topv  [BGR*256];
__device__ int   g_newidx[NTMAX];

// ---------------- small kernels ----------------
__global__ void k_zero_out(float* out, int n) {
    int i = blockIdx.x*blockDim.x + threadIdx.x;
    if (i < n) out[i] = 0.f;
}
__global__ void k_copy_edges(const int* __restrict__ ei, int* __restrict__ src,
                             int* __restrict__ dst) {
    int e = blockIdx.x*blockDim.x + threadIdx.x;
    if (e < ETOT) { src[e] = ei[e]; dst[e] = ei[ETOT + e]; }
}
__global__ void k_zero2(int* a, int* b, int n) {
    int i = blockIdx.x*blockDim.x + threadIdx.x;
    if (i < n) { a[i] = 0; b[i] = 0; }
}
__global__ void k_count(const int* __restrict__ dst, int* __restrict__ cnt) {
    int e = blockIdx.x*blockDim.x + threadIdx.x;
    if (e < ETOT) { int d = dst[e]; if (d >= 0) atomicAdd(&cnt[d], 1); }
}
__global__ void k_dinv(const int* __restrict__ cnt, float* __restrict__ dinv, int nt) {
    int i = blockIdx.x*blockDim.x + threadIdx.x;
    if (i < nt) dinv[i] = rsqrtf((float)cnt[i] + 1.0f);
}
// per-graph exclusive scan of in-degree counts -> CSR offsets (base = graph*EPG)
__global__ void k_scan(const int* __restrict__ cnt, int n, int* __restrict__ off) {
    __shared__ int sm[512];
    int b = blockIdx.x, i = threadIdx.x;
    int c = cnt[b*n + i];
    sm[i] = c;
    __syncthreads();
    for (int s = 1; s < n; s <<= 1) {
        int t = (i >= s) ? sm[i - s] : 0;
        __syncthreads();
        sm[i] += t;
        __syncthreads();
    }
    off[b*n + i] = b*EPG + sm[i] - c;
}
__global__ void k_fill(const int* __restrict__ src, const int* __restrict__ dst,
                       const int* __restrict__ off, int* __restrict__ cursor,
                       const float* __restrict__ dinv,
                       int* __restrict__ csr_src, float* __restrict__ csr_w) {
    int e = blockIdx.x*blockDim.x + threadIdx.x;
    if (e >= ETOT) return;
    int d = dst[e]; if (d < 0) return;
    int s = src[e];
    int pos = off[d] + atomicAdd(&cursor[d], 1);
    csr_src[pos] = s;
    csr_w[pos]   = dinv[s] * dinv[d];
}

// ---------------- SGEMM: C[M,128] = A[M,128] @ W[128,128] ----------------
__global__ __launch_bounds__(256) void k_gemm(const float* __restrict__ A,
                                              const float* __restrict__ W,
                                              float* __restrict__ C) {
    __shared__ float As[16][128];
    __shared__ float Bs[16][128];
    int t = threadIdx.x;
    int row0 = blockIdx.x * 128;
    int lr = t >> 1, lk = (t & 1) << 3;       // A loader: row, k-offset
    int bk = t >> 4, bn = (t & 15) << 3;      // W loader
    int ty = t >> 4, tx = t & 15;             // 8x8 micro-tile coords
    float acc[8][8];
#pragma unroll
    for (int i = 0; i < 8; i++)
#pragma unroll
        for (int j = 0; j < 8; j++) acc[i][j] = 0.f;

    for (int k0 = 0; k0 < 128; k0 += 16) {
        float4 a0 = *(const float4*)(A + (row0 + lr)*128 + k0 + lk);
        float4 a1 = *(const float4*)(A + (row0 + lr)*128 + k0 + lk + 4);
        As[lk+0][lr] = a0.x; As[lk+1][lr] = a0.y; As[lk+2][lr] = a0.z; As[lk+3][lr] = a0.w;
        As[lk+4][lr] = a1.x; As[lk+5][lr] = a1.y; As[lk+6][lr] = a1.z; As[lk+7][lr] = a1.w;
        *(float4*)&Bs[bk][bn]     = *(const float4*)(W + (k0 + bk)*128 + bn);
        *(float4*)&Bs[bk][bn + 4] = *(const float4*)(W + (k0 + bk)*128 + bn + 4);
        __syncthreads();
#pragma unroll
        for (int kk = 0; kk < 16; kk++) {
            float ra[8], rb[8];
#pragma unroll
            for (int i = 0; i < 8; i++) ra[i] = As[kk][ty*8 + i];
#pragma unroll
            for (int j = 0; j < 8; j++) rb[j] = Bs[kk][tx*8 + j];
#pragma unroll
            for (int i = 0; i < 8; i++)
#pragma unroll
                for (int j = 0; j < 8; j++) acc[i][j] += ra[i] * rb[j];
        }
        __syncthreads();
    }
#pragma unroll
    for (int i = 0; i < 8; i++) {
        float4 v0 = make_float4(acc[i][0], acc[i][1], acc[i][2], acc[i][3]);
        float4 v1 = make_float4(acc[i][4], acc[i][5], acc[i][6], acc[i][7]);
        *(float4*)(C + (row0 + ty*8 + i)*128 + tx*8)     = v0;
        *(float4*)(C + (row0 + ty*8 + i)*128 + tx*8 + 4) = v1;
    }
}

// ---------------- aggregation + ReLU + fused score GEMV ----------------
// h[i] = relu(b + dinv[i]^2 * h0[i] + sum_j w_j * h0[src_j]); s0[i] = h[i] . Ws
__global__ __launch_bounds__(256) void k_agg(const float* __restrict__ h0,
                                             const float* __restrict__ bias,
                                             const float* __restrict__ dinv,
                                             const int* __restrict__ cnt,
                                             const int* __restrict__ off,
                                             const int* __restrict__ csr_src,
                                             const float* __restrict__ csr_w,
                                             const float* __restrict__ Ws,
                                             float* __restrict__ h,
                                             float* __restrict__ s0, int nt) {
    int warp = (blockIdx.x*blockDim.x + threadIdx.x) >> 5;
    int lane = threadIdx.x & 31;
    if (warp >= nt) return;
    int i = warp;
    float di = dinv[i];
    float self = di * di;
    float4 acc = *(const float4*)(bias + lane*4);
    float4 hv  = *(const float4*)(h0 + (size_t)i*128 + lane*4);
    acc.x += self*hv.x; acc.y += self*hv.y; acc.z += self*hv.z; acc.w += self*hv.w;
    int o = off[i], c = cnt[i];
    for (int j = 0; j < c; j++) {
        int   s = csr_src[o + j];
        float w = csr_w[o + j];
        float4 hs = *(const float4*)(h0 + (size_t)s*128 + lane*4);
        acc.x += w*hs.x; acc.y += w*hs.y; acc.z += w*hs.z; acc.w += w*hs.w;
    }
    acc.x = fmaxf(acc.x, 0.f); acc.y = fmaxf(acc.y, 0.f);
    acc.z = fmaxf(acc.z, 0.f); acc.w = fmaxf(acc.w, 0.f);
    *(float4*)(h + (size_t)i*128 + lane*4) = acc;
    float4 ws = *(const float4*)(Ws + lane*4);
    float p = acc.x*ws.x + acc.y*ws.y + acc.z*ws.z + acc.w*ws.w;
#pragma unroll
    for (int d = 16; d; d >>= 1) p += __shfl_xor_sync(0xFFFFFFFFu, p, d);
    if (lane == 0) s0[i] = p;
}

// score[i] = bs + dinv[i]^2*s0[i] + sum_j w_j * s0[src_j]
__global__ void k_score(const float* __restrict__ s0, const float* __restrict__ dinv,
                        const int* __restrict__ cnt, const int* __restrict__ off,
                        const int* __restrict__ csr_src, const float* __restrict__ csr_w,
                        const float* __restrict__ bs, float* __restrict__ score, int nt) {
    int i = blockIdx.x*blockDim.x + threadIdx.x;
    if (i >= nt) return;
    float di = dinv[i];
    float acc = bs[0] + di*di*s0[i];
    int o = off[i], c = cnt[i];
    for (int j = 0; j < c; j++) acc += csr_w[o + j] * s0[csr_src[o + j]];
    score[i] = acc;
}

// per-graph exact top-k via bitonic sort (desc score, asc index ties)
__global__ void k_topk(const float* __restrict__ score, int n, int k,
                       int* __restrict__ topi, float* __restrict__ topv,
                       int* __restrict__ newidx) {
    __shared__ unsigned long long keys[512];
    int b = blockIdx.x, i = threadIdx.x;
    float s = score[b*n + i];
    unsigned u  = __float_as_uint(s);
    unsigned ou = u ^ ((u & 0x80000000u) ? 0xFFFFFFFFu : 0x80000000u); // order-preserving
    keys[i] = ((unsigned long long)(~ou) << 32) | (unsigned)i;         // asc sort => desc score
    __syncthreads();
    for (int kk = 2; kk <= n; kk <<= 1) {
        for (int j = kk >> 1; j > 0; j >>= 1) {
            int ixj = i ^ j;
            if (ixj > i) {
                bool up = ((i & kk) == 0);
                unsigned long long a = keys[i], c = keys[ixj];
                if ((a > c) == up) { keys[i] = c; keys[ixj] = a; }
            }
            __syncthreads();
        }
    }
    unsigned long long kx = keys[i];
    int idx = (int)(kx & 0xFFFFFFFFull);
    if (i < k) {
        topi[b*k + i] = idx;
        topv[b*k + i] = score[b*n + idx];
        newidx[b*n + idx] = b*k + i;
    } else {
        newidx[b*n + idx] = -1;
    }
}

// xnew[j] = h[old(j)] * tanh(topv[j])
__global__ __launch_bounds__(256) void k_xnew(const float* __restrict__ h,
                                              const int* __restrict__ topi,
                                              const float* __restrict__ topv,
                                              float* __restrict__ xnew,
                                              int n, int k, int M) {
    int warp = (blockIdx.x*blockDim.x + threadIdx.x) >> 5;
    int lane = threadIdx.x & 31;
    if (warp >= M) return;
    int b   = warp / k;
    int old = topi[warp];
    float t = tanhf(topv[warp]);
    float4 v = *(const float4*)(h + (size_t)(b*n + old)*128 + lane*4);
    v.x *= t; v.y *= t; v.z *= t; v.w *= t;
    *(float4*)(xnew + (size_t)warp*128 + lane*4) = v;
}

// out[b, 0:128] += max_j xnew ; out[b, 128:256] += mean_j xnew
__global__ void k_readout(const float* __restrict__ xnew, float* __restrict__ out, int k) {
    int b = blockIdx.x, c = threadIdx.x;
    float mx = -3.402823466e38f, sm = 0.f;
    for (int j = 0; j < k; j++) {
        float v = xnew[(size_t)(b*k + j)*128 + c];
        mx = fmaxf(mx, v); sm += v;
    }
    out[b*256 + c]       += mx;
    out[b*256 + 128 + c] += sm / (float)k;
}

__global__ void k_remap(int* __restrict__ src, int* __restrict__ dst,
                        const int* __restrict__ newidx) {
    int e = blockIdx.x*blockDim.x + threadIdx.x;
    if (e >= ETOT) return;
    int d = dst[e]; if (d < 0) return;
    int s  = src[e];
    int ns = newidx[s], nd = newidx[d];
    if (ns < 0 || nd < 0) dst[e] = -1;
    else { src[e] = ns; dst[e] = nd; }
}

// ---------------- host-side stage driver ----------------
struct Ptrs {
    float *bufA, *bufB, *dinv, *s0, *score, *csrw, *topv;
    int *src, *dst, *csrs, *cnt, *cursor, *off, *topi, *newidx;
};

static void run_stage(const float* X, float* H0, float* H, float* XN,
                      const float* W, const float* bias,
                      const float* Ws, const float* bs,
                      int n, int k, float* out, bool do_remap, const Ptrs& P) {
    int NT = BGR * n;
    int M  = BGR * k;
    k_zero2 <<<(NT + 255)/256, 256>>>(P.cnt, P.cursor, NT);
    k_count <<<(ETOT + 255)/256, 256>>>(P.dst, P.cnt);
    k_dinv  <<<(NT + 255)/256, 256>>>(P.cnt, P.dinv, NT);
    k_scan  <<<BGR, n>>>(P.cnt, n, P.off);
    k_fill  <<<(ETOT + 255)/256, 256>>>(P.src, P.dst, P.off, P.cursor, P.dinv, P.csrs, P.csrw);
    k_gemm  <<<NT/128, 256>>>(X, W, H0);
    k_agg   <<<NT/8, 256>>>(H0, bias, P.dinv, P.cnt, P.off, P.csrs, P.csrw, Ws, H, P.s0, NT);
    k_score <<<(NT + 255)/256, 256>>>(P.s0, P.dinv, P.cnt, P.off, P.csrs, P.csrw, bs, P.score, NT);
    k_topk  <<<BGR, n>>>(P.score, n, k, P.topi, P.topv, P.newidx);
    k_xnew  <<<M/8, 256>>>(H, P.topi, P.topv, XN, n, k, M);
    k_readout<<<BGR, 128>>>(XN, out, k);
    if (do_remap) k_remap<<<(ETOT + 255)/256, 256>>>(P.src, P.dst, P.newidx);
}

extern "C" void kernel_launch(void* const* d_in, const int* in_sizes, int n_in,
                              void* d_out, int out_size) {
    const float* x   = (const float*)d_in[0];
    const int*   ei  = (const int*)  d_in[1];
    const float* W1  = (const float*)d_in[3];
    const float* b1  = (const float*)d_in[4];
    const float* Ws1 = (const float*)d_in[5];
    const float* bs1 = (const float*)d_in[6];
    const float* W2  = (const float*)d_in[7];
    const float* b2  = (const float*)d_in[8];
    const float* Ws2 = (const float*)d_in[9];
    const float* bs2 = (const float*)d_in[10];
    const float* W3  = (const float*)d_in[11];
    const float* b3  = (const float*)d_in[12];
    const float* Ws3 = (const float*)d_in[13];
    const float* bs3 = (const float*)d_in[14];
    float* out = (float*)d_out;

    Ptrs P;
    cudaGetSymbolAddress((void**)&P.bufA,   g_bufA);
    cudaGetSymbolAddress((void**)&P.bufB,   g_bufB);
    cudaGetSymbolAddress((void**)&P.dinv,   g_dinv);
    cudaGetSymbolAddress((void**)&P.s0,     g_s0);
    cudaGetSymbolAddress((void**)&P.score,  g_score);
    cudaGetSymbolAddress((void**)&P.csrw,   g_csr_w);
    cudaGetSymbolAddress((void**)&P.topv,   g_topv);
    cudaGetSymbolAddress((void**)&P.src,    g_src);
    cudaGetSymbolAddress((void**)&P.dst,    g_dst);
    cudaGetSymbolAddress((void**)&P.csrs,   g_csr_src);
    cudaGetSymbolAddress((void**)&P.cnt,    g_cnt);
    cudaGetSymbolAddress((void**)&P.cursor, g_cursor);
    cudaGetSymbolAddress((void**)&P.off,    g_off);
    cudaGetSymbolAddress((void**)&P.topi,   g_topi);
    cudaGetSymbolAddress((void**)&P.newidx, g_newidx);

    k_zero_out<<<(out_size + 255)/256, 256>>>(out, out_size);
    k_copy_edges<<<(ETOT + 255)/256, 256>>>(ei, P.src, P.dst);

    // stage 1: X = input x,  h0 = bufB, h = bufA, xnew = bufB
    run_stage(x,      P.bufB, P.bufA, P.bufB, W1, b1, Ws1, bs1, 512, 256, out, true,  P);
    // stage 2: X = bufB, h0 = bufA, h = bufB, xnew = bufA
    run_stage(P.bufB, P.bufA, P.bufB, P.bufA, W2, b2, Ws2, bs2, 256, 128, out, true,  P);
    // stage 3: X = bufA, h0 = bufB, h = bufA, xnew = bufB  (no remap needed)
    run_stage(P.bufA, P.bufB, P.bufA, P.bufB, W3, b3, Ws3, bs3, 128,  64, out, false, P);
}

// round 2
// speedup vs baseline: 1.1587x; 1.1587x over previous
#include <cuda_runtime.h>
#include <cuda_bf16.h>
#include <cstdint>

#define BGR   128          // graphs
#define EPG   4096         // edges per graph
#define ETOT  (BGR*EPG)    // 524288 edges
#define FDIM  128
#define NTMAX (BGR*512)    // 65536 max nodes

// ---------------- device scratch ----------------
__device__ float g_bufA[NTMAX*FDIM];   // Xa (aggregated input)
__device__ float g_bufB[NTMAX*FDIM];   // H  (post-GEMM features)
__device__ float g_bufC[NTMAX*FDIM];   // xnew (next-stage input)
__device__ float g_s0   [NTMAX];
__device__ int   g_src[ETOT];
__device__ int   g_dst[ETOT];
__device__ int   g_csr_src[ETOT];
__device__ float g_csr_w [ETOT];
__device__ int   g_cnt   [NTMAX];
__device__ int   g_off   [NTMAX];
__device__ int   g_topi  [BGR*256];
__device__ float g_topt  [BGR*256];    // tanh(topv)
__device__ int   g_newidx[NTMAX];

// =====================================================================
// Fused per-graph prep: remap + mask + count + dinv + scan + CSR fill
// =====================================================================
template<int NPG, int REMAP, int WRITEBACK>
__global__ __launch_bounds__(512)
void k_prep(const int* __restrict__ esrc, const int* __restrict__ edst,
            const int* __restrict__ newidx,
            int* __restrict__ osrc, int* __restrict__ odst,
            int* __restrict__ cnt, int* __restrict__ off,
            int* __restrict__ csr_src, float* __restrict__ csr_w) {
    __shared__ int   s_cnt [NPG];
    __shared__ int   s_cur [NPG];
    __shared__ float s_dinv[NPG];
    const int b = blockIdx.x, t = threadIdx.x;
    const int ebase = b * EPG;
    const int nbase = b * NPG;
    if (t < NPG) s_cnt[t] = 0;
    __syncthreads();

    int ls[8], ldst[8];
#pragma unroll
    for (int u = 0; u < 8; u++) {
        int e = ebase + u*512 + t;
        int s = esrc[e], d = edst[e];
        if (REMAP) {
            if (d >= 0) {
                int ns = newidx[s], nd = newidx[d];
                if (ns < 0 || nd < 0) d = -1;
                else { s = ns; d = nd; }
            }
        }
        if (WRITEBACK) { osrc[e] = s; odst[e] = d; }
        if (d >= 0) {
            ls[u]   = s - nbase;
            ldst[u] = d - nbase;
            atomicAdd(&s_cnt[ldst[u]], 1);
        } else ldst[u] = -1;
    }
    __syncthreads();

    int c = (t < NPG) ? s_cnt[t] : 0;
    if (t < NPG) {
        cnt[nbase + t] = c;
        s_dinv[t] = rsqrtf((float)c + 1.f);
        s_cur[t]  = c;
    }
    __syncthreads();
    // Hillis-Steele inclusive scan over NPG entries
    for (int sft = 1; sft < NPG; sft <<= 1) {
        int add = (t >= sft && t < NPG) ? s_cur[t - sft] : 0;
        __syncthreads();
        if (t < NPG) s_cur[t] += add;
        __syncthreads();
    }
    if (t < NPG) {
        int o = s_cur[t] - c;            // exclusive prefix
        off[nbase + t] = ebase + o;
        s_cur[t] = o;                    // becomes cursor
    }
    __syncthreads();

#pragma unroll
    for (int u = 0; u < 8; u++) {
        if (ldst[u] >= 0) {
            int pos = ebase + atomicAdd(&s_cur[ldst[u]], 1);
            csr_src[pos] = nbase + ls[u];                  // global src id
            csr_w [pos]  = s_dinv[ls[u]] * s_dinv[ldst[u]];
        }
    }
}

// =====================================================================
// Aggregation on input features: Xa[i] = X[i]/(deg+1) + sum_j w_ij X[j]
// one warp per node, 4-way unrolled gathers (MLP=4)
// =====================================================================
__global__ __launch_bounds__(256)
void k_agg(const float* __restrict__ X, const int* __restrict__ cnt,
           const int* __restrict__ off, const int* __restrict__ csr_src,
           const float* __restrict__ csr_w, float* __restrict__ Xa, int nt) {
    int warp = (blockIdx.x*256 + threadIdx.x) >> 5;
    int lane = threadIdx.x & 31;
    if (warp >= nt) return;
    int i = warp;
    int c = cnt[i], o = off[i];
    float self = 1.f / ((float)c + 1.f);
    float4 hv = *(const float4*)(X + (size_t)i*128 + lane*4);
    float4 a0 = make_float4(self*hv.x, self*hv.y, self*hv.z, self*hv.w);
    float4 a1 = make_float4(0,0,0,0), a2 = make_float4(0,0,0,0), a3 = make_float4(0,0,0,0);
    int j = 0;
    for (; j + 4 <= c; j += 4) {
        int   s0 = csr_src[o+j],   s1 = csr_src[o+j+1];
        int   s2 = csr_src[o+j+2], s3 = csr_src[o+j+3];
        float w0 = csr_w[o+j],   w1 = csr_w[o+j+1];
        float w2 = csr_w[o+j+2], w3 = csr_w[o+j+3];
        float4 h0 = *(const float4*)(X + (size_t)s0*128 + lane*4);
        float4 h1 = *(const float4*)(X + (size_t)s1*128 + lane*4);
        float4 h2 = *(const float4*)(X + (size_t)s2*128 + lane*4);
        float4 h3 = *(const float4*)(X + (size_t)s3*128 + lane*4);
        a0.x += w0*h0.x; a0.y += w0*h0.y; a0.z += w0*h0.z; a0.w += w0*h0.w;
        a1.x += w1*h1.x; a1.y += w1*h1.y; a1.z += w1*h1.z; a1.w += w1*h1.w;
        a2.x += w2*h2.x; a2.y += w2*h2.y; a2.z += w2*h2.z; a2.w += w2*h2.w;
        a3.x += w3*h3.x; a3.y += w3*h3.y; a3.z += w3*h3.z; a3.w += w3*h3.w;
    }
    for (; j < c; j++) {
        int s = csr_src[o+j]; float w = csr_w[o+j];
        float4 hs = *(const float4*)(X + (size_t)s*128 + lane*4);
        a0.x += w*hs.x; a0.y += w*hs.y; a0.z += w*hs.z; a0.w += w*hs.w;
    }
    a0.x += a1.x + a2.x + a3.x;
    a0.y += a1.y + a2.y + a3.y;
    a0.z += a1.z + a2.z + a3.z;
    a0.w += a1.w + a2.w + a3.w;
    *(float4*)(Xa + (size_t)i*128 + lane*4) = a0;
}

// =====================================================================
// GEMM: H[M,128] = relu(Xa @ W + b), epilogue also computes s0 = H.Ws
// =====================================================================
__global__ __launch_bounds__(256)
void k_gemm(const float* __restrict__ A, const float* __restrict__ W,
            const float* __restrict__ bias, const float* __restrict__ Ws,
            float* __restrict__ C, float* __restrict__ s0) {
    __shared__ float As[16][128];
    __shared__ float Bs[16][128];
    int t = threadIdx.x;
    int row0 = blockIdx.x * 128;
    int lr = t >> 1, lk = (t & 1) << 3;
    int bk = t >> 4, bn = (t & 15) << 3;
    int ty = t >> 4, tx = t & 15;
    float acc[8][8];
#pragma unroll
    for (int i = 0; i < 8; i++)
#pragma unroll
        for (int j = 0; j < 8; j++) acc[i][j] = 0.f;

    for (int k0 = 0; k0 < 128; k0 += 16) {
        float4 a0 = *(const float4*)(A + (size_t)(row0 + lr)*128 + k0 + lk);
        float4 a1 = *(const float4*)(A + (size_t)(row0 + lr)*128 + k0 + lk + 4);
        As[lk+0][lr] = a0.x; As[lk+1][lr] = a0.y; As[lk+2][lr] = a0.z; As[lk+3][lr] = a0.w;
        As[lk+4][lr] = a1.x; As[lk+5][lr] = a1.y; As[lk+6][lr] = a1.z; As[lk+7][lr] = a1.w;
        *(float4*)&Bs[bk][bn]     = *(const float4*)(W + (k0 + bk)*128 + bn);
        *(float4*)&Bs[bk][bn + 4] = *(const float4*)(W + (k0 + bk)*128 + bn + 4);
        __syncthreads();
#pragma unroll
        for (int kk = 0; kk < 16; kk++) {
            float ra[8], rb[8];
#pragma unroll
            for (int i = 0; i < 8; i++) ra[i] = As[kk][ty*8 + i];
#pragma unroll
            for (int j = 0; j < 8; j++) rb[j] = Bs[kk][tx*8 + j];
#pragma unroll
            for (int i = 0; i < 8; i++)
#pragma unroll
                for (int j = 0; j < 8; j++) acc[i][j] += ra[i] * rb[j];
        }
        __syncthreads();
    }
    float bb[8], ws[8];
#pragma unroll
    for (int j = 0; j < 8; j++) { bb[j] = bias[tx*8 + j]; ws[j] = Ws[tx*8 + j]; }
#pragma unroll
    for (int i = 0; i < 8; i++) {
#pragma unroll
        for (int j = 0; j < 8; j++) acc[i][j] = fmaxf(acc[i][j] + bb[j], 0.f);
        float4 v0 = make_float4(acc[i][0], acc[i][1], acc[i][2], acc[i][3]);
        float4 v1 = make_float4(acc[i][4], acc[i][5], acc[i][6], acc[i][7]);
        *(float4*)(C + (size_t)(row0 + ty*8 + i)*128 + tx*8)     = v0;
        *(float4*)(C + (size_t)(row0 + ty*8 + i)*128 + tx*8 + 4) = v1;
        float p = 0.f;
#pragma unroll
        for (int j = 0; j < 8; j++) p += acc[i][j] * ws[j];
#pragma unroll
        for (int d = 1; d < 16; d <<= 1) p += __shfl_xor_sync(0xFFFFFFFFu, p, d);
        if ((t & 15) == 0) s0[row0 + ty*8 + i] = p;
    }
}

// =====================================================================
// Fused score-GCN + per-graph exact top-k (bitonic)
// =====================================================================
template<int NPG>
__global__ void k_topk(const int* __restrict__ cnt, const int* __restrict__ off,
                       const int* __restrict__ csr_src, const float* __restrict__ csr_w,
                       const float* __restrict__ s0, const float* __restrict__ bs,
                       int* __restrict__ topi, float* __restrict__ topt,
                       int* __restrict__ newidx) {
    constexpr int K = NPG/2;
    __shared__ unsigned long long keys[NPG];
    __shared__ float s_sc[NPG];
    int b = blockIdx.x, i = threadIdx.x;
    int gi = b*NPG + i;
    int c = cnt[gi], o = off[gi];
    float acc = bs[0] + s0[gi] / ((float)c + 1.f);
    for (int j = 0; j < c; j++) acc += csr_w[o+j] * s0[csr_src[o+j]];
    s_sc[i] = acc;
    unsigned u  = __float_as_uint(acc);
    unsigned ou = u ^ ((u & 0x80000000u) ? 0xFFFFFFFFu : 0x80000000u);
    keys[i] = ((unsigned long long)(~ou) << 32) | (unsigned)i;  // asc => desc score, asc idx
    __syncthreads();
    for (int kk = 2; kk <= NPG; kk <<= 1) {
        for (int j = kk >> 1; j > 0; j >>= 1) {
            int ixj = i ^ j;
            if (ixj > i) {
                bool up = ((i & kk) == 0);
                unsigned long long a = keys[i], cc = keys[ixj];
                if ((a > cc) == up) { keys[i] = cc; keys[ixj] = a; }
            }
            __syncthreads();
        }
    }
    int idx = (int)(keys[i] & 0xFFFFFFFFull);
    if (i < K) {
        topi[b*K + i] = idx;
        topt[b*K + i] = tanhf(s_sc[idx]);
        newidx[b*NPG + idx] = b*K + i;
    } else {
        newidx[b*NPG + idx] = -1;
    }
}

// =====================================================================
// Fused gather*tanh + readout (max / mean), writes xnew for next stage
// =====================================================================
template<int NPG, int ACCUM>
__global__ __launch_bounds__(128)
void k_xr(const float* __restrict__ H, const int* __restrict__ topi,
          const float* __restrict__ topt, float* __restrict__ xnew,
          float* __restrict__ out) {
    constexpr int K = NPG/2;
    __shared__ int   s_old[K];
    __shared__ float s_t  [K];
    int b = blockIdx.x, cth = threadIdx.x;
    for (int j = cth; j < K; j += 128) { s_old[j] = topi[b*K + j]; s_t[j] = topt[b*K + j]; }
    __syncthreads();
    float mx = -3.402823466e38f, sm = 0.f;
    for (int j = 0; j < K; j++) {
        float v = H[(size_t)(b*NPG + s_old[j])*128 + cth] * s_t[j];
        xnew[(size_t)(b*K + j)*128 + cth] = v;
        mx = fmaxf(mx, v); sm += v;
    }
    if (ACCUM) {
        out[b*256 + cth]       += mx;
        out[b*256 + 128 + cth] += sm / (float)K;
    } else {
        out[b*256 + cth]       = mx;
        out[b*256 + 128 + cth] = sm / (float)K;
    }
}

// =====================================================================
extern "C" void kernel_launch(void* const* d_in, const int* in_sizes, int n_in,
                              void* d_out, int out_size) {
    const float* x   = (const float*)d_in[0];
    const int*   ei  = (const int*)  d_in[1];
    const float* W1  = (const float*)d_in[3];
    const float* b1  = (const float*)d_in[4];
    const float* Ws1 = (const float*)d_in[5];
    const float* bs1 = (const float*)d_in[6];
    const float* W2  = (const float*)d_in[7];
    const float* b2  = (const float*)d_in[8];
    const float* Ws2 = (const float*)d_in[9];
    const float* bs2 = (const float*)d_in[10];
    const float* W3  = (const float*)d_in[11];
    const float* b3  = (const float*)d_in[12];
    const float* Ws3 = (const float*)d_in[13];
    const float* bs3 = (const float*)d_in[14];
    float* out = (float*)d_out;

    float *bufA, *bufB, *bufC, *s0p, *csrw, *topt;
    int *srcp, *dstp, *csrs, *cntp, *offp, *topip, *newip;
    cudaGetSymbolAddress((void**)&bufA,  g_bufA);
    cudaGetSymbolAddress((void**)&bufB,  g_bufB);
    cudaGetSymbolAddress((void**)&bufC,  g_bufC);
    cudaGetSymbolAddress((void**)&s0p,   g_s0);
    cudaGetSymbolAddress((void**)&csrw,  g_csr_w);
    cudaGetSymbolAddress((void**)&topt,  g_topt);
    cudaGetSymbolAddress((void**)&srcp,  g_src);
    cudaGetSymbolAddress((void**)&dstp,  g_dst);
    cudaGetSymbolAddress((void**)&csrs,  g_csr_src);
    cudaGetSymbolAddress((void**)&cntp,  g_cnt);
    cudaGetSymbolAddress((void**)&offp,  g_off);
    cudaGetSymbolAddress((void**)&topip, g_topi);
    cudaGetSymbolAddress((void**)&newip, g_newidx);

    const int* ei_src = ei;
    const int* ei_dst = ei + ETOT;

    // ---------------- stage 1: n=512, k=256 ----------------
    {
        const int NT = BGR*512;
        k_prep<512,0,0><<<BGR,512>>>(ei_src, ei_dst, newip, srcp, dstp,
                                     cntp, offp, csrs, csrw);
        k_agg <<<NT/8,256>>>(x, cntp, offp, csrs, csrw, bufA, NT);
        k_gemm<<<NT/128,256>>>(bufA, W1, b1, Ws1, bufB, s0p);
        k_topk<512><<<BGR,512>>>(cntp, offp, csrs, csrw, s0p, bs1, topip, topt, newip);
        k_xr<512,0><<<BGR,128>>>(bufB, topip, topt, bufC, out);
    }
    // ---------------- stage 2: n=256, k=128 ----------------
    {
        const int NT = BGR*256;
        k_prep<256,1,1><<<BGR,512>>>(ei_src, ei_dst, newip, srcp, dstp,
                                     cntp, offp, csrs, csrw);
        k_agg <<<NT/8,256>>>(bufC, cntp, offp, csrs, csrw, bufA, NT);
        k_gemm<<<NT/128,256>>>(bufA, W2, b2, Ws2, bufB, s0p);
        k_topk<256><<<BGR,256>>>(cntp, offp, csrs, csrw, s0p, bs2, topip, topt, newip);
        k_xr<256,1><<<BGR,128>>>(bufB, topip, topt, bufC, out);
    }
    // ---------------- stage 3: n=128, k=64 ----------------
    {
        const int NT = BGR*128;
        k_prep<128,1,0><<<BGR,512>>>(srcp, dstp, newip, srcp, dstp,
                                     cntp, offp, csrs, csrw);
        k_agg <<<NT/8,256>>>(bufC, cntp, offp, csrs, csrw, bufA, NT);
        k_gemm<<<NT/128,256>>>(bufA, W3, b3, Ws3, bufB, s0p);
        k_topk<128><<<BGR,128>>>(cntp, offp, csrs, csrw, s0p, bs3, topip, topt, newip);
        k_xr<128,1><<<BGR,128>>>(bufB, topip, topt, bufC, out);
    }
}